// round 13
// baseline (speedup 1.0000x reference)
#include <cuda_runtime.h>
#include <cstdint>

// ZGate (qudit diagonal phase): D=4, S=1, INDEX=(0,2,5,8), L=10, B=16.
// phase(n) = i^p. For float4 index i (n = i>>2):
//   p = ((i>>20)+(i>>16)+(i>>10)+(i>>4)) & 3
// Output (verified) = REAL part only, [N, B] float32:
//   p=0 -> +re   p=1 -> -im   p=2 -> -re   p=3 -> +im
// R12: raise in-flight memory per thread (MLP=8). Plane select folded into a
// single 32-bit uint4 index against the xre base (saves 8 pointers of regs);
// store index recomputed. One balanced persistent wave. __ldcg / __stcs.

constexpr int VPT = 8;                     // uint4 per thread per tile
constexpr int THREADS = 256;
constexpr unsigned TILE = THREADS * VPT;   // 2048 uint4 per tile
constexpr unsigned MAX_WAVE_BLOCKS = 148u * 8u;

__global__ __launch_bounds__(THREADS) void zgate_mlp8_kernel(
    const uint4* __restrict__ xre,         // imag plane at xre + plane4
    uint4* __restrict__ out,
    unsigned plane4,                       // total uint4 per plane
    unsigned total4)                       // == plane4, multiple of TILE here
{
    const unsigned tile_stride = gridDim.x * TILE;

    for (unsigned t0 = blockIdx.x * TILE + threadIdx.x; t0 < total4;
         t0 += tile_stride) {

        unsigned a[VPT];    // load index into xre base (plane folded in)
        unsigned m[VPT];    // sign mask
        uint4 v[VPT];

#pragma unroll
        for (int k = 0; k < VPT; k++) {
            const unsigned i = t0 + k * (unsigned)THREADS;
            const unsigned p =
                ((i >> 20) + (i >> 16) + (i >> 10) + (i >> 4)) & 3u;
            a[k] = i + ((p & 1u) ? plane4 : 0u);
            m[k] = (p == 1u || p == 2u) ? 0x80000000u : 0u;
        }
#pragma unroll
        for (int k = 0; k < VPT; k++) v[k] = __ldcg(xre + a[k]);
#pragma unroll
        for (int k = 0; k < VPT; k++) {
            const unsigned i = t0 + k * (unsigned)THREADS;  // recompute (IMAD)
            uint4 o;
            o.x = v[k].x ^ m[k];
            o.y = v[k].y ^ m[k];
            o.z = v[k].z ^ m[k];
            o.w = v[k].w ^ m[k];
            __stcs(out + i, o);
        }
    }
}

// Guarded single-pass variant for sizes not a multiple of TILE.
__global__ __launch_bounds__(THREADS) void zgate_guard_kernel(
    const uint4* __restrict__ xre,
    uint4* __restrict__ out, unsigned plane4, unsigned total4)
{
    const unsigned base = blockIdx.x * TILE + threadIdx.x;
#pragma unroll
    for (int k = 0; k < VPT; k++) {
        const unsigned i = base + k * (unsigned)THREADS;
        if (i >= total4) continue;
        const unsigned p = ((i >> 20) + (i >> 16) + (i >> 10) + (i >> 4)) & 3u;
        const unsigned m = (p == 1u || p == 2u) ? 0x80000000u : 0u;
        uint4 v = __ldcg(xre + i + ((p & 1u) ? plane4 : 0u));
        v.x ^= m; v.y ^= m; v.z ^= m; v.w ^= m;
        __stcs(out + i, v);
    }
}

// ---- fallbacks for other output layouts (defensive, unchanged) ----

__device__ __forceinline__ void phase_cs(unsigned n, float& c, float& s) {
    const unsigned p = ((n >> 18) + (n >> 14) + (n >> 8) + (n >> 2)) & 3u;
    c = (float)((p == 0u) - (p == 2u));
    s = (float)((p == 1u) - (p == 3u));
}

__global__ __launch_bounds__(256) void zgate_planar_kernel(
    const float4* __restrict__ xre, const float4* __restrict__ xim,
    float4* __restrict__ outre, float4* __restrict__ outim, long long total4)
{
    const long long t = (long long)blockIdx.x * blockDim.x + threadIdx.x;
    if (t >= total4) return;
    const unsigned n = (unsigned)(t >> 2);
    float c, s; phase_cs(n, c, s);
    const float4 re = xre[t], im = xim[t];
    float4 oR, oI;
    oR.x = c * re.x - s * im.x;  oI.x = s * re.x + c * im.x;
    oR.y = c * re.y - s * im.y;  oI.y = s * re.y + c * im.y;
    oR.z = c * re.z - s * im.z;  oI.z = s * re.z + c * im.z;
    oR.w = c * re.w - s * im.w;  oI.w = s * re.w + c * im.w;
    outre[t] = oR;
    outim[t] = oI;
}

__global__ __launch_bounds__(256) void zgate_safe_kernel(
    const float* __restrict__ x, float* __restrict__ out,
    long long plane, long long out_floats)
{
    const long long e = (long long)blockIdx.x * blockDim.x + threadIdx.x;
    if (e >= plane) return;
    const unsigned n = (unsigned)(e >> 4);
    float c, s; phase_cs(n, c, s);
    const float re = x[e], im = x[plane + e];
    const long long o = 2 * e;
    if (o < out_floats)     out[o]     = c * re - s * im;
    if (o + 1 < out_floats) out[o + 1] = s * re + c * im;
}

extern "C" void kernel_launch(void* const* d_in, const int* in_sizes, int n_in,
                              void* d_out, int out_size) {
    const float* x = (const float*)d_in[0];             // [2, N, B]
    const long long plane = (long long)in_sizes[0] / 2; // N*B floats per plane

    if ((long long)out_size == plane) {
        const long long total4 = plane / 4;             // uint4 per plane
        if (total4 % TILE == 0 && total4 < (1LL << 31)) {
            const unsigned ntiles = (unsigned)(total4 / TILE);
            unsigned blocks = ntiles <= MAX_WAVE_BLOCKS ? ntiles : 0;
            if (!blocks) {
                for (unsigned b = 1024u; b >= 1u; b >>= 1) {
                    if (ntiles % b == 0) { blocks = b; break; }
                }
                if (blocks < 256u) {
                    for (unsigned b = MAX_WAVE_BLOCKS; b >= 1u; b--) {
                        if (ntiles % b == 0) { blocks = b; break; }
                    }
                }
            }
            zgate_mlp8_kernel<<<blocks, THREADS>>>(
                (const uint4*)x, (uint4*)d_out,
                (unsigned)total4, (unsigned)total4);
        } else {
            const int blocks = (int)((total4 + TILE - 1) / TILE);
            zgate_guard_kernel<<<blocks, THREADS>>>(
                (const uint4*)x, (uint4*)d_out,
                (unsigned)total4, (unsigned)total4);
        }
    } else if ((long long)out_size == 2 * plane) {
        float* out = (float*)d_out;
        const long long total4 = plane / 4;
        const int blocks = (int)((total4 + 255) / 256);
        zgate_planar_kernel<<<blocks, 256>>>(
            (const float4*)x, (const float4*)(x + plane),
            (float4*)out, (float4*)(out + plane), total4);
    } else {
        const int blocks = (int)((plane + 255) / 256);
        zgate_safe_kernel<<<blocks, 256>>>(x, (float*)d_out, plane,
                                           (long long)out_size);
    }
}

// round 14
// speedup vs baseline: 1.1235x; 1.1235x over previous
#include <cuda_runtime.h>
#include <cstdint>

// ZGate (qudit diagonal phase): D=4, S=1, INDEX=(0,2,5,8), L=10, B=16.
// phase(n) = i^p. For float4 index i (n = i>>2):
//   p = ((i>>20)+(i>>16)+(i>>10)+(i>>4)) & 3
// Output (verified) = REAL part only, [N, B] float32:
//   p=0 -> +re   p=1 -> -im   p=2 -> -re   p=3 -> +im
// R13: MLP=8 inner loop (R12, kernel-fastest) + strictly one resident wave.
// regs=56 -> 4 blocks/SM -> wave budget 592 blocks; use 512 blocks x 4 tiles
// (perfect balance). __ldcg / __stcs, consecutive lanes, k block-strided.

constexpr int VPT = 8;                     // uint4 per thread per tile
constexpr int THREADS = 256;
constexpr unsigned TILE = THREADS * VPT;   // 2048 uint4 per tile
constexpr unsigned WAVE_BLOCKS_MLP8 = 148u * 4u;   // occ limit at 56 regs

__global__ __launch_bounds__(THREADS) void zgate_mlp8_kernel(
    const uint4* __restrict__ xre,         // imag plane at xre + plane4
    uint4* __restrict__ out,
    unsigned plane4,
    unsigned total4)
{
    const unsigned tile_stride = gridDim.x * TILE;

    for (unsigned t0 = blockIdx.x * TILE + threadIdx.x; t0 < total4;
         t0 += tile_stride) {

        unsigned a[VPT];
        unsigned m[VPT];
        uint4 v[VPT];

#pragma unroll
        for (int k = 0; k < VPT; k++) {
            const unsigned i = t0 + k * (unsigned)THREADS;
            const unsigned p =
                ((i >> 20) + (i >> 16) + (i >> 10) + (i >> 4)) & 3u;
            a[k] = i + ((p & 1u) ? plane4 : 0u);
            m[k] = (p == 1u || p == 2u) ? 0x80000000u : 0u;
        }
#pragma unroll
        for (int k = 0; k < VPT; k++) v[k] = __ldcg(xre + a[k]);
#pragma unroll
        for (int k = 0; k < VPT; k++) {
            const unsigned i = t0 + k * (unsigned)THREADS;
            uint4 o;
            o.x = v[k].x ^ m[k];
            o.y = v[k].y ^ m[k];
            o.z = v[k].z ^ m[k];
            o.w = v[k].w ^ m[k];
            __stcs(out + i, o);
        }
    }
}

// Guarded single-pass variant for sizes not a multiple of TILE.
__global__ __launch_bounds__(THREADS) void zgate_guard_kernel(
    const uint4* __restrict__ xre,
    uint4* __restrict__ out, unsigned plane4, unsigned total4)
{
    const unsigned base = blockIdx.x * TILE + threadIdx.x;
#pragma unroll
    for (int k = 0; k < VPT; k++) {
        const unsigned i = base + k * (unsigned)THREADS;
        if (i >= total4) continue;
        const unsigned p = ((i >> 20) + (i >> 16) + (i >> 10) + (i >> 4)) & 3u;
        const unsigned m = (p == 1u || p == 2u) ? 0x80000000u : 0u;
        uint4 v = __ldcg(xre + i + ((p & 1u) ? plane4 : 0u));
        v.x ^= m; v.y ^= m; v.z ^= m; v.w ^= m;
        __stcs(out + i, v);
    }
}

// ---- fallbacks for other output layouts (defensive, unchanged) ----

__device__ __forceinline__ void phase_cs(unsigned n, float& c, float& s) {
    const unsigned p = ((n >> 18) + (n >> 14) + (n >> 8) + (n >> 2)) & 3u;
    c = (float)((p == 0u) - (p == 2u));
    s = (float)((p == 1u) - (p == 3u));
}

__global__ __launch_bounds__(256) void zgate_planar_kernel(
    const float4* __restrict__ xre, const float4* __restrict__ xim,
    float4* __restrict__ outre, float4* __restrict__ outim, long long total4)
{
    const long long t = (long long)blockIdx.x * blockDim.x + threadIdx.x;
    if (t >= total4) return;
    const unsigned n = (unsigned)(t >> 2);
    float c, s; phase_cs(n, c, s);
    const float4 re = xre[t], im = xim[t];
    float4 oR, oI;
    oR.x = c * re.x - s * im.x;  oI.x = s * re.x + c * im.x;
    oR.y = c * re.y - s * im.y;  oI.y = s * re.y + c * im.y;
    oR.z = c * re.z - s * im.z;  oI.z = s * re.z + c * im.z;
    oR.w = c * re.w - s * im.w;  oI.w = s * re.w + c * im.w;
    outre[t] = oR;
    outim[t] = oI;
}

__global__ __launch_bounds__(256) void zgate_safe_kernel(
    const float* __restrict__ x, float* __restrict__ out,
    long long plane, long long out_floats)
{
    const long long e = (long long)blockIdx.x * blockDim.x + threadIdx.x;
    if (e >= plane) return;
    const unsigned n = (unsigned)(e >> 4);
    float c, s; phase_cs(n, c, s);
    const float re = x[e], im = x[plane + e];
    const long long o = 2 * e;
    if (o < out_floats)     out[o]     = c * re - s * im;
    if (o + 1 < out_floats) out[o + 1] = s * re + c * im;
}

extern "C" void kernel_launch(void* const* d_in, const int* in_sizes, int n_in,
                              void* d_out, int out_size) {
    const float* x = (const float*)d_in[0];             // [2, N, B]
    const long long plane = (long long)in_sizes[0] / 2; // N*B floats per plane

    if ((long long)out_size == plane) {
        const long long total4 = plane / 4;             // uint4 per plane
        if (total4 % TILE == 0 && total4 < (1LL << 31)) {
            const unsigned ntiles = (unsigned)(total4 / TILE);  // 2048 here
            // Largest power-of-two divisor of ntiles within ONE wave at the
            // MLP8 kernel's occupancy (4 blocks/SM -> 592); 512 for ntiles=2048.
            unsigned blocks = ntiles;
            while (blocks > WAVE_BLOCKS_MLP8) blocks >>= 1;
            if (blocks == 0) blocks = 1;
            // ensure divisibility (power-of-two ntiles makes this exact)
            while (ntiles % blocks != 0) blocks >>= 1;
            zgate_mlp8_kernel<<<blocks, THREADS>>>(
                (const uint4*)x, (uint4*)d_out,
                (unsigned)total4, (unsigned)total4);
        } else {
            const int blocks = (int)((total4 + TILE - 1) / TILE);
            zgate_guard_kernel<<<blocks, THREADS>>>(
                (const uint4*)x, (uint4*)d_out,
                (unsigned)total4, (unsigned)total4);
        }
    } else if ((long long)out_size == 2 * plane) {
        float* out = (float*)d_out;
        const long long total4 = plane / 4;
        const int blocks = (int)((total4 + 255) / 256);
        zgate_planar_kernel<<<blocks, 256>>>(
            (const float4*)x, (const float4*)(x + plane),
            (float4*)out, (float4*)(out + plane), total4);
    } else {
        const int blocks = (int)((plane + 255) / 256);
        zgate_safe_kernel<<<blocks, 256>>>(x, (float*)d_out, plane,
                                           (long long)out_size);
    }
}